// round 12
// baseline (speedup 1.0000x reference)
#include <cuda_runtime.h>
#include <cstddef>

#define Bn 16
#define Cn 320
#define Hn 64
#define Wn 64
#define HWn 4096          // Hn*Wn
#define PIXn (Bn*HWn)     // 65536 pixels
#define SPLIT 8
#define CPS (Cn / SPLIT)  // 40 channels per split

// Scratch (allocation-free requirement -> __device__ globals)
__device__ __align__(16) float g_part[SPLIT * PIXn]; // partial channel sums (2MB)
__device__ __align__(16) float g_w0[PIXn];           // softmax weight0 [B,H,W]

// ---------------------------------------------------------------------------
// k1: partial channel sums, 8-way C split, float4 (one thread per 4 pixels).
// Empirically best mean config (~17.0us at the part's ~5.05TB/s stream
// ceiling = its floor). __ldcs: eg has zero reuse -> don't occupy L2.
// ---------------------------------------------------------------------------
__global__ void __launch_bounds__(256) k_mean_part(const float* __restrict__ eg) {
    int idx = blockIdx.x * blockDim.x + threadIdx.x;  // < SPLIT*PIXn/4 = 131072
    int q = idx & 16383;            // quad index within one split's pixel set
    int s = idx >> 14;              // split 0..7
    int b = q >> 10;                // 1024 quads per image plane
    int hw4 = q & 1023;
    const float4* ptr = (const float4*)eg
                      + (size_t)b * Cn * (HWn / 4)
                      + (size_t)s * CPS * (HWn / 4) + hw4;
    float4 a0 = make_float4(0.f, 0.f, 0.f, 0.f), a1 = a0, a2 = a0, a3 = a0;
#pragma unroll
    for (int c = 0; c < CPS; c += 4) {
        float4 v0 = __ldcs(ptr + (size_t)(c + 0) * (HWn / 4));
        float4 v1 = __ldcs(ptr + (size_t)(c + 1) * (HWn / 4));
        float4 v2 = __ldcs(ptr + (size_t)(c + 2) * (HWn / 4));
        float4 v3 = __ldcs(ptr + (size_t)(c + 3) * (HWn / 4));
        a0.x += v0.x; a0.y += v0.y; a0.z += v0.z; a0.w += v0.w;
        a1.x += v1.x; a1.y += v1.y; a1.z += v1.z; a1.w += v1.w;
        a2.x += v2.x; a2.y += v2.y; a2.z += v2.z; a2.w += v2.w;
        a3.x += v3.x; a3.y += v3.y; a3.z += v3.z; a3.w += v3.w;
    }
    float4 r;
    r.x = (a0.x + a1.x) + (a2.x + a3.x);
    r.y = (a0.y + a1.y) + (a2.y + a3.y);
    r.z = (a0.z + a1.z) + (a2.z + a3.z);
    r.w = (a0.w + a1.w) + (a2.w + a3.w);
    ((float4*)g_part)[idx] = r;     // layout: g_part[s*PIXn + p]
}

// ---------------------------------------------------------------------------
// k_gate: fused  mean-finalize -> conv1(1->16)+relu -> conv2(16->2) -> sigmoid
// One block per 16x16 output tile; 512 threads so every smem stage is a
// single pass (400 / 324 / 256 items) -> half the dependent-latency chain
// of the 256-thread version.
// ---------------------------------------------------------------------------
#define TS 16
#define EMD 20            // em tile dim (TS + 2*2 halo)
#define HD 18             // h tile dim  (TS + 2*1 halo)
#define HPOS (HD * HD)    // 324

__global__ void __launch_bounds__(512) k_gate(
        const float* __restrict__ w1, const float* __restrict__ b1,
        const float* __restrict__ w2, const float* __restrict__ b2) {
    __shared__ float s_em[EMD * EMD];
    __shared__ float s_h[16 * HPOS];      // [c][pos]
    __shared__ float s_w1[160];           // 144 weights + 16 bias
    __shared__ float s_w2[290];           // 288 weights + 2 bias

    int tid = threadIdx.x;
    if (tid < 144)            s_w1[tid] = w1[tid];
    else if (tid < 160)       s_w1[tid] = b1[tid - 144];
    else if (tid >= 224)      s_w2[tid - 224] = w2[tid - 224];   // covers [0,288)
    if (tid < 2)              s_w2[288 + tid] = b2[tid];

    int blk = blockIdx.x;
    int b   = blk >> 4;                 // 16 tiles per batch image
    int ty0 = ((blk >> 2) & 3) * TS;
    int tx0 = (blk & 3) * TS;

    // ---- stage 1: em tile with 2-halo, mean from the 8 partials (1 pass) ----
    if (tid < EMD * EMD) {
        int iy = tid / EMD, ix = tid - iy * EMD;
        int gy = ty0 + iy - 2, gx = tx0 + ix - 2;
        float v = 0.f;
        if ((unsigned)gy < (unsigned)Hn && (unsigned)gx < (unsigned)Wn) {
            int p = b * HWn + gy * Wn + gx;
            float s = 0.f;
#pragma unroll
            for (int k = 0; k < SPLIT; ++k)
                s += g_part[k * PIXn + p];
            v = s * (1.0f / (float)Cn);
        }
        s_em[tid] = v;
    }
    __syncthreads();

    // ---- stage 2: conv1 + relu at 18x18 positions (1 pass) ----
    if (tid < HPOS) {
        int iy = tid / HD, ix = tid - iy * HD;
        int gy = ty0 + iy - 1, gx = tx0 + ix - 1;
        if ((unsigned)gy < (unsigned)Hn && (unsigned)gx < (unsigned)Wn) {
            float patch[9];
#pragma unroll
            for (int dy = 0; dy < 3; ++dy)
#pragma unroll
                for (int dx = 0; dx < 3; ++dx)
                    patch[dy * 3 + dx] = s_em[(iy + dy) * EMD + (ix + dx)];
#pragma unroll
            for (int c = 0; c < 16; ++c) {
                float a = s_w1[144 + c];
#pragma unroll
                for (int k = 0; k < 9; ++k)
                    a = fmaf(s_w1[c * 9 + k], patch[k], a);
                s_h[c * HPOS + tid] = fmaxf(a, 0.f);
            }
        } else {
#pragma unroll
            for (int c = 0; c < 16; ++c)
                s_h[c * HPOS + tid] = 0.f;   // conv2 SAME padding
        }
    }
    __syncthreads();

    // ---- stage 3: conv2 + sigmoid, one pixel per thread (tid < 256) ----
    if (tid < TS * TS) {
        int iy = tid >> 4, ix = tid & 15;
        float l0 = s_w2[288], l1 = s_w2[289];
#pragma unroll
        for (int ky = 0; ky < 3; ++ky) {
#pragma unroll
            for (int kx = 0; kx < 3; ++kx) {
                int pos = (iy + ky) * HD + (ix + kx);
                int koff = ky * 3 + kx;
#pragma unroll
                for (int c = 0; c < 16; ++c) {
                    float hv = s_h[c * HPOS + pos];
                    l0 = fmaf(s_w2[c * 9 + koff], hv, l0);
                    l1 = fmaf(s_w2[144 + c * 9 + koff], hv, l1);
                }
            }
        }
        g_w0[b * HWn + (ty0 + iy) * Wn + (tx0 + ix)] =
            1.0f / (1.0f + expf(l1 - l0));
    }
}

// ---------------------------------------------------------------------------
// k_shift: out = w0 * x[h - sh[g], w] + (1-w0) * x[h, w - sw[g]] (zero-fill)
// 8 floats (two aligned float4) per thread; 8 threads per 64-float row.
// Branchless h-load (clamped + masked) so all 6 float4 loads batch at the
// top; w-shift via warp shuffles; streaming stores. At its DRAM floor.
// ---------------------------------------------------------------------------
__global__ void __launch_bounds__(256) k_shift(const float* __restrict__ x,
                        const int* __restrict__ shv,
                        const int* __restrict__ swv,
                        float* __restrict__ out) {
    int idx = blockIdx.x * blockDim.x + threadIdx.x;  // < B*C*H*(W/8) = 2621440
    int seg = idx & 7;            // 8-float segment within row
    int h   = (idx >> 3) & 63;
    int t   = idx >> 9;           // b*Cn + c ; uniform across warp
    int b   = t / Cn;
    int c   = t - b * Cn;
    int g   = c >> 6;             // 64 channels per group
    int sh  = __ldg(shv + g);
    int sw  = __ldg(swv + g);
    int L   = threadIdx.x & 7;    // thread position within row (== seg)

    size_t base = (size_t)t * HWn;

    int hh = h - sh;
    bool hok = (unsigned)hh < (unsigned)Hn;
    int hc = hok ? hh : h;        // safe row (masked below)
    float m = hok ? 1.f : 0.f;

    // issue all global loads up front
    const float4* rowp = (const float4*)(x + base + h * Wn) + seg * 2;
    const float4* rp2  = (const float4*)(x + base + hc * Wn) + seg * 2;
    const float4* wp   = (const float4*)(g_w0 + b * HWn + h * Wn) + seg * 2;
    float4 A0 = rowp[0];
    float4 A1 = rowp[1];
    float4 h0 = rp2[0];
    float4 h1 = rp2[1];
    float4 g0 = wp[0];
    float4 g1 = wp[1];

    float a0 = A0.x, a1 = A0.y, a2 = A0.z, a3 = A0.w;
    float a4 = A1.x, a5 = A1.y, a6 = A1.z, a7 = A1.w;

    // neighbor boundary values for the w-shift
    float pl0 = __shfl_up_sync(0xffffffffu, a6, 1);   // a[-2]
    float pl1 = __shfl_up_sync(0xffffffffu, a7, 1);   // a[-1]
    float nr0 = __shfl_down_sync(0xffffffffu, a0, 1); // a[8]
    float nr1 = __shfl_down_sync(0xffffffffu, a1, 1); // a[9]

    float w0, w1, w2, w3, w4, w5, w6, w7;
    if (sw == 0) {
        w0 = a0; w1 = a1; w2 = a2; w3 = a3; w4 = a4; w5 = a5; w6 = a6; w7 = a7;
    } else if (sw == 1) {
        w0 = (L > 0) ? pl1 : 0.f;
        w1 = a0; w2 = a1; w3 = a2; w4 = a3; w5 = a4; w6 = a5; w7 = a6;
    } else if (sw == 2) {
        w0 = (L > 0) ? pl0 : 0.f;
        w1 = (L > 0) ? pl1 : 0.f;
        w2 = a0; w3 = a1; w4 = a2; w5 = a3; w6 = a4; w7 = a5;
    } else if (sw == -1) {
        w0 = a1; w1 = a2; w2 = a3; w3 = a4; w4 = a5; w5 = a6; w6 = a7;
        w7 = (L < 7) ? nr0 : 0.f;
    } else { // sw == -2
        w0 = a2; w1 = a3; w2 = a4; w3 = a5; w4 = a6; w5 = a7;
        w6 = (L < 7) ? nr0 : 0.f;
        w7 = (L < 7) ? nr1 : 0.f;
    }

    float4 o0, o1;
    o0.x = g0.x * (m * h0.x) + (1.f - g0.x) * w0;
    o0.y = g0.y * (m * h0.y) + (1.f - g0.y) * w1;
    o0.z = g0.z * (m * h0.z) + (1.f - g0.z) * w2;
    o0.w = g0.w * (m * h0.w) + (1.f - g0.w) * w3;
    o1.x = g1.x * (m * h1.x) + (1.f - g1.x) * w4;
    o1.y = g1.y * (m * h1.y) + (1.f - g1.y) * w5;
    o1.z = g1.z * (m * h1.z) + (1.f - g1.z) * w6;
    o1.w = g1.w * (m * h1.w) + (1.f - g1.w) * w7;

    float4* op = (float4*)(out + base + h * Wn) + seg * 2;
    __stcs(op,     o0);   // streaming store: out never re-read
    __stcs(op + 1, o1);
}

// ---------------------------------------------------------------------------
extern "C" void kernel_launch(void* const* d_in, const int* in_sizes, int n_in,
                              void* d_out, int out_size) {
    const float* x   = (const float*)d_in[0];
    const float* eg  = (const float*)d_in[1];
    const float* w1  = (const float*)d_in[2];
    const float* b1  = (const float*)d_in[3];
    const float* w2  = (const float*)d_in[4];
    const float* b2  = (const float*)d_in[5];
    const int*   shv = (const int*)d_in[6];
    const int*   swv = (const int*)d_in[7];
    float* out = (float*)d_out;

    k_mean_part<<<512, 256>>>(eg);                  // 131072 threads
    k_gate     <<<256, 512>>>(w1, b1, w2, b2);      // 131072 threads
    k_shift    <<<10240, 256>>>(x, shv, swv, out);  // 2,621,440 threads
}

// round 13
// speedup vs baseline: 1.1617x; 1.1617x over previous
#include <cuda_runtime.h>
#include <cstddef>

#define Bn 16
#define Cn 320
#define Hn 64
#define Wn 64
#define HWn 4096          // Hn*Wn
#define PIXn (Bn*HWn)     // 65536 pixels
#define SPLIT 8
#define CPS (Cn / SPLIT)  // 40 channels per split

// Scratch (allocation-free requirement -> __device__ globals)
__device__ __align__(16) float g_part[SPLIT * PIXn]; // partial channel sums (2MB)
__device__ __align__(16) float g_w0[PIXn];           // softmax weight0 [B,H,W]

// ---------------------------------------------------------------------------
// k1: partial channel sums, 8-way C split, float4 (one thread per 4 pixels).
// Empirically best mean config (~17.0us at the part's ~5.05TB/s stream
// ceiling = its floor). __ldcs: eg has zero reuse -> don't occupy L2.
// ---------------------------------------------------------------------------
__global__ void __launch_bounds__(256) k_mean_part(const float* __restrict__ eg) {
    int idx = blockIdx.x * blockDim.x + threadIdx.x;  // < SPLIT*PIXn/4 = 131072
    int q = idx & 16383;            // quad index within one split's pixel set
    int s = idx >> 14;              // split 0..7
    int b = q >> 10;                // 1024 quads per image plane
    int hw4 = q & 1023;
    const float4* ptr = (const float4*)eg
                      + (size_t)b * Cn * (HWn / 4)
                      + (size_t)s * CPS * (HWn / 4) + hw4;
    float4 a0 = make_float4(0.f, 0.f, 0.f, 0.f), a1 = a0, a2 = a0, a3 = a0;
#pragma unroll
    for (int c = 0; c < CPS; c += 4) {
        float4 v0 = __ldcs(ptr + (size_t)(c + 0) * (HWn / 4));
        float4 v1 = __ldcs(ptr + (size_t)(c + 1) * (HWn / 4));
        float4 v2 = __ldcs(ptr + (size_t)(c + 2) * (HWn / 4));
        float4 v3 = __ldcs(ptr + (size_t)(c + 3) * (HWn / 4));
        a0.x += v0.x; a0.y += v0.y; a0.z += v0.z; a0.w += v0.w;
        a1.x += v1.x; a1.y += v1.y; a1.z += v1.z; a1.w += v1.w;
        a2.x += v2.x; a2.y += v2.y; a2.z += v2.z; a2.w += v2.w;
        a3.x += v3.x; a3.y += v3.y; a3.z += v3.z; a3.w += v3.w;
    }
    float4 r;
    r.x = (a0.x + a1.x) + (a2.x + a3.x);
    r.y = (a0.y + a1.y) + (a2.y + a3.y);
    r.z = (a0.z + a1.z) + (a2.z + a3.z);
    r.w = (a0.w + a1.w) + (a2.w + a3.w);
    ((float4*)g_part)[idx] = r;     // layout: g_part[s*PIXn + p]
}

// ---------------------------------------------------------------------------
// k_gate: fused  mean-finalize -> conv1(1->16)+relu -> conv2(16->2) -> sigmoid
// One block per 16x16 output tile (256 blocks, 256 threads).
// ---------------------------------------------------------------------------
#define TS 16
#define EMD 20            // em tile dim (TS + 2*2 halo)
#define HD 18             // h tile dim  (TS + 2*1 halo)
#define HPOS (HD * HD)    // 324

__global__ void k_gate(const float* __restrict__ w1, const float* __restrict__ b1,
                       const float* __restrict__ w2, const float* __restrict__ b2) {
    __shared__ float s_em[EMD * EMD];
    __shared__ float s_h[16 * HPOS];      // [c][pos]
    __shared__ float s_w1[160];           // 144 weights + 16 bias
    __shared__ float s_w2[290];           // 288 weights + 2 bias

    int tid = threadIdx.x;
    if (tid < 144)       s_w1[tid] = w1[tid];
    else if (tid < 160)  s_w1[tid] = b1[tid - 144];
    for (int i = tid; i < 288; i += 256) s_w2[i] = w2[i];
    if (tid < 2) s_w2[288 + tid] = b2[tid];

    int blk = blockIdx.x;
    int b   = blk >> 4;                 // 16 tiles per batch image
    int ty0 = ((blk >> 2) & 3) * TS;
    int tx0 = (blk & 3) * TS;

    // ---- stage 1: em tile with 2-halo, mean computed from partials ----
    for (int i = tid; i < EMD * EMD; i += 256) {
        int iy = i / EMD, ix = i - iy * EMD;
        int gy = ty0 + iy - 2, gx = tx0 + ix - 2;
        float v = 0.f;
        if ((unsigned)gy < (unsigned)Hn && (unsigned)gx < (unsigned)Wn) {
            int p = b * HWn + gy * Wn + gx;
            float s = 0.f;
#pragma unroll
            for (int k = 0; k < SPLIT; ++k)
                s += g_part[k * PIXn + p];
            v = s * (1.0f / (float)Cn);
        }
        s_em[i] = v;
    }
    __syncthreads();

    // ---- stage 2: conv1 + relu at 18x18 positions ----
    for (int i = tid; i < HPOS; i += 256) {
        int iy = i / HD, ix = i - iy * HD;
        int gy = ty0 + iy - 1, gx = tx0 + ix - 1;
        if ((unsigned)gy < (unsigned)Hn && (unsigned)gx < (unsigned)Wn) {
            float patch[9];
#pragma unroll
            for (int dy = 0; dy < 3; ++dy)
#pragma unroll
                for (int dx = 0; dx < 3; ++dx)
                    patch[dy * 3 + dx] = s_em[(iy + dy) * EMD + (ix + dx)];
#pragma unroll
            for (int c = 0; c < 16; ++c) {
                float a = s_w1[144 + c];
#pragma unroll
                for (int k = 0; k < 9; ++k)
                    a = fmaf(s_w1[c * 9 + k], patch[k], a);
                s_h[c * HPOS + i] = fmaxf(a, 0.f);
            }
        } else {
#pragma unroll
            for (int c = 0; c < 16; ++c)
                s_h[c * HPOS + i] = 0.f;     // conv2 SAME padding
        }
    }
    __syncthreads();

    // ---- stage 3: conv2 + sigmoid, one pixel per thread ----
    int iy = tid >> 4, ix = tid & 15;
    float l0 = s_w2[288], l1 = s_w2[289];
#pragma unroll
    for (int ky = 0; ky < 3; ++ky) {
#pragma unroll
        for (int kx = 0; kx < 3; ++kx) {
            int pos = (iy + ky) * HD + (ix + kx);
            int koff = ky * 3 + kx;
#pragma unroll
            for (int c = 0; c < 16; ++c) {
                float hv = s_h[c * HPOS + pos];
                l0 = fmaf(s_w2[c * 9 + koff], hv, l0);
                l1 = fmaf(s_w2[144 + c * 9 + koff], hv, l1);
            }
        }
    }
    g_w0[b * HWn + (ty0 + iy) * Wn + (tx0 + ix)] = 1.0f / (1.0f + expf(l1 - l0));
}

// ---------------------------------------------------------------------------
// k_shift: out = w0 * x[h - sh[g], w] + (1-w0) * x[h, w - sw[g]] (zero-fill)
// 8 floats (two aligned float4) per thread; 8 threads per 64-float row.
// Branchless h-load (clamped + masked) so all 6 float4 loads batch at the
// top; w-shift via warp shuffles; streaming stores. At its DRAM floor.
// ---------------------------------------------------------------------------
__global__ void __launch_bounds__(256) k_shift(const float* __restrict__ x,
                        const int* __restrict__ shv,
                        const int* __restrict__ swv,
                        float* __restrict__ out) {
    int idx = blockIdx.x * blockDim.x + threadIdx.x;  // < B*C*H*(W/8) = 2621440
    int seg = idx & 7;            // 8-float segment within row
    int h   = (idx >> 3) & 63;
    int t   = idx >> 9;           // b*Cn + c ; uniform across warp
    int b   = t / Cn;
    int c   = t - b * Cn;
    int g   = c >> 6;             // 64 channels per group
    int sh  = __ldg(shv + g);
    int sw  = __ldg(swv + g);
    int L   = threadIdx.x & 7;    // thread position within row (== seg)

    size_t base = (size_t)t * HWn;

    int hh = h - sh;
    bool hok = (unsigned)hh < (unsigned)Hn;
    int hc = hok ? hh : h;        // safe row (masked below)
    float m = hok ? 1.f : 0.f;

    // issue all global loads up front
    const float4* rowp = (const float4*)(x + base + h * Wn) + seg * 2;
    const float4* rp2  = (const float4*)(x + base + hc * Wn) + seg * 2;
    const float4* wp   = (const float4*)(g_w0 + b * HWn + h * Wn) + seg * 2;
    float4 A0 = rowp[0];
    float4 A1 = rowp[1];
    float4 h0 = rp2[0];
    float4 h1 = rp2[1];
    float4 g0 = wp[0];
    float4 g1 = wp[1];

    float a0 = A0.x, a1 = A0.y, a2 = A0.z, a3 = A0.w;
    float a4 = A1.x, a5 = A1.y, a6 = A1.z, a7 = A1.w;

    // neighbor boundary values for the w-shift
    float pl0 = __shfl_up_sync(0xffffffffu, a6, 1);   // a[-2]
    float pl1 = __shfl_up_sync(0xffffffffu, a7, 1);   // a[-1]
    float nr0 = __shfl_down_sync(0xffffffffu, a0, 1); // a[8]
    float nr1 = __shfl_down_sync(0xffffffffu, a1, 1); // a[9]

    float w0, w1, w2, w3, w4, w5, w6, w7;
    if (sw == 0) {
        w0 = a0; w1 = a1; w2 = a2; w3 = a3; w4 = a4; w5 = a5; w6 = a6; w7 = a7;
    } else if (sw == 1) {
        w0 = (L > 0) ? pl1 : 0.f;
        w1 = a0; w2 = a1; w3 = a2; w4 = a3; w5 = a4; w6 = a5; w7 = a6;
    } else if (sw == 2) {
        w0 = (L > 0) ? pl0 : 0.f;
        w1 = (L > 0) ? pl1 : 0.f;
        w2 = a0; w3 = a1; w4 = a2; w5 = a3; w6 = a4; w7 = a5;
    } else if (sw == -1) {
        w0 = a1; w1 = a2; w2 = a3; w3 = a4; w4 = a5; w5 = a6; w6 = a7;
        w7 = (L < 7) ? nr0 : 0.f;
    } else { // sw == -2
        w0 = a2; w1 = a3; w2 = a4; w3 = a5; w4 = a6; w5 = a7;
        w6 = (L < 7) ? nr0 : 0.f;
        w7 = (L < 7) ? nr1 : 0.f;
    }

    float4 o0, o1;
    o0.x = g0.x * (m * h0.x) + (1.f - g0.x) * w0;
    o0.y = g0.y * (m * h0.y) + (1.f - g0.y) * w1;
    o0.z = g0.z * (m * h0.z) + (1.f - g0.z) * w2;
    o0.w = g0.w * (m * h0.w) + (1.f - g0.w) * w3;
    o1.x = g1.x * (m * h1.x) + (1.f - g1.x) * w4;
    o1.y = g1.y * (m * h1.y) + (1.f - g1.y) * w5;
    o1.z = g1.z * (m * h1.z) + (1.f - g1.z) * w6;
    o1.w = g1.w * (m * h1.w) + (1.f - g1.w) * w7;

    float4* op = (float4*)(out + base + h * Wn) + seg * 2;
    __stcs(op,     o0);   // streaming store: out never re-read
    __stcs(op + 1, o1);
}

// ---------------------------------------------------------------------------
extern "C" void kernel_launch(void* const* d_in, const int* in_sizes, int n_in,
                              void* d_out, int out_size) {
    const float* x   = (const float*)d_in[0];
    const float* eg  = (const float*)d_in[1];
    const float* w1  = (const float*)d_in[2];
    const float* b1  = (const float*)d_in[3];
    const float* w2  = (const float*)d_in[4];
    const float* b2  = (const float*)d_in[5];
    const int*   shv = (const int*)d_in[6];
    const int*   swv = (const int*)d_in[7];
    float* out = (float*)d_out;

    k_mean_part<<<512, 256>>>(eg);                  // 131072 threads
    k_gate     <<<256, 256>>>(w1, b1, w2, b2);      // 65536 threads
    k_shift    <<<10240, 256>>>(x, shv, swv, out);  // 2,621,440 threads
}